// round 15
// baseline (speedup 1.0000x reference)
#include <cuda_runtime.h>
#include <cuda_fp16.h>

#define Nn 10000
#define Ee 100000
#define Cc 32
#define Gg 64
#define BN_EPS 1e-5f
#define NBLK 148

typedef unsigned long long u64;
typedef unsigned int u32;

// ---- scratch (static device globals; zero-initialized at load) ----
__device__ __align__(16) u64   g_T2[(size_t)Nn * 256];   // 20.48 MB fp16 T
__device__ __align__(16) float g_xb[Nn * Cc];
__device__ __align__(16) float g_xr[Nn * Cc];
__device__ __align__(16) float g_agg[Nn * Cc];
__device__ float g_deg[Nn];
__device__ __align__(16) float g_pool[Gg * Cc];
__device__ float g_pcnt[Gg];
__device__ unsigned g_cnt;                 // barrier count (self-resetting)
__device__ unsigned g_sense;               // barrier sense (monotonic; replay-safe)

__device__ __forceinline__ void red_add_v4(float* addr, float a, float b, float c, float d) {
    asm volatile("red.global.add.v4.f32 [%0], {%1, %2, %3, %4};"
                 :: "l"(addr), "f"(a), "f"(b), "f"(c), "f"(d) : "memory");
}
__device__ __forceinline__ u32 h2pack(float lo, float hi) {
    __half2 h = __floats2half2_rn(lo, hi);
    return *(u32*)&h;
}
__device__ __forceinline__ void mma16816(float c[4], u32 a0, u32 a1, u32 a2, u32 a3,
                                         u32 b0, u32 b1) {
    asm("mma.sync.aligned.m16n8k16.row.col.f32.f16.f16.f32 "
        "{%0,%1,%2,%3}, {%4,%5,%6,%7}, {%8,%9}, {%0,%1,%2,%3};"
        : "+f"(c[0]), "+f"(c[1]), "+f"(c[2]), "+f"(c[3])
        : "r"(a0), "r"(a1), "r"(a2), "r"(a3), "r"(b0), "r"(b1));
}

// ---- grid barrier: sense-reversing, count self-reset by last arriver ----
__device__ __forceinline__ void gbar() {
    __syncthreads();
    if (threadIdx.x == 0) {
        __threadfence();
        unsigned s = *(volatile unsigned*)&g_sense;
        unsigned old = atomicAdd(&g_cnt, 1u);
        if (old == NBLK - 1) {
            g_cnt = 0;
            __threadfence();
            atomicAdd(&g_sense, 1u);
        } else {
            while (*(volatile unsigned*)&g_sense == s) {}
        }
        __threadfence();
    }
    __syncthreads();
}

// ---- phase: T = x@w2 (HMMA) + xb = x@b2 (warps 0-3) + xr = x@root + bias (warps 4-7).
// L1 (bg==null): input = xin, fused deg histogram (ei != null).
// L2 (bg!=null): input tile = BN1(agg/deg + xr) ReLU on the fly; resets agg.
__device__ void phase_T(const float* __restrict__ xin, const float* __restrict__ w2,
                        const float* __restrict__ b2, const float* __restrict__ root,
                        const float* __restrict__ bias, const int* __restrict__ ei,
                        const float* __restrict__ bg, const float* __restrict__ bb,
                        const float* __restrict__ bm, const float* __restrict__ bv,
                        __half* xs, u64* ts) {
    int tid = threadIdx.x;
    int lane = tid & 31;
    int w = tid >> 5;
    int tg = lane & 3;
    int gr = lane >> 2;
    bool l2 = (bg != nullptr);

    if (ei) {
        for (int e = blockIdx.x * 512 + tid; e < Ee; e += NBLK * 512)
            atomicAdd(&g_deg[__ldg(&ei[Ee + e])], 1.f);
    }

    u32 Bf[4][2][2][2];
#pragma unroll
    for (int q = 0; q < 4; q++)
#pragma unroll
        for (int kk = 0; kk < 2; kk++) {
            const float* rb = w2 + (2 * w + kk) * 1024 + q * 8 + gr;
#pragma unroll
            for (int st = 0; st < 2; st++) {
                int i0 = 2 * tg + 16 * st;
                Bf[q][kk][st][0] = h2pack(__ldg(&rb[i0 * 32]),       __ldg(&rb[(i0 + 1) * 32]));
                Bf[q][kk][st][1] = h2pack(__ldg(&rb[(i0 + 8) * 32]), __ldg(&rb[(i0 + 9) * 32]));
            }
        }
    u32 Bs[2][2] = {};
    float2 biasv = make_float2(0.f, 0.f);
    if (w < 8) {
        const float* src = (w < 4) ? (b2 + w * 8 + gr) : (root + (w - 4) * 8 + gr);
#pragma unroll
        for (int st = 0; st < 2; st++) {
            int i0 = 2 * tg + 16 * st;
            Bs[st][0] = h2pack(__ldg(&src[i0 * 32]),       __ldg(&src[(i0 + 1) * 32]));
            Bs[st][1] = h2pack(__ldg(&src[(i0 + 8) * 32]), __ldg(&src[(i0 + 9) * 32]));
        }
        if (w >= 4) biasv = __ldg((const float2*)(bias + (w - 4) * 8 + 2 * tg));
    }

    float scale = 0.f, shift = 0.f;
    if (l2) {
        int i = tid & 31;
        float s = rsqrtf(__ldg(&bv[i]) + BN_EPS) * __ldg(&bg[i]);
        scale = s;
        shift = __ldg(&bb[i]) - __ldg(&bm[i]) * s;
    }

    int tile = blockIdx.x;
    float pA = 0.f, pX = 0.f;
    if (tile < 625) {
        if (l2) { pA = g_agg[tile * 512 + tid]; pX = g_xr[tile * 512 + tid]; }
        else      pA = __ldg(&xin[tile * 512 + tid]);
    }

    for (; tile < 625; tile += NBLK) {
        int nb = tile * 16;
        int j = tid >> 5, i = tid & 31;
        float xv;
        if (l2) {
            float dg = fmaxf(g_deg[nb + j], 1.f);
            xv = fmaxf((pA / dg + pX) * scale + shift, 0.f);
            g_agg[tile * 512 + tid] = 0.f;
        } else xv = pA;
        xs[j * 40 + i] = __float2half(xv);
        __syncthreads();

        const u32* xp = (const u32*)xs;
        int ab = gr * 20 + tg;
        u32 a0 = xp[ab],       a1 = xp[ab + 160];
        u32 a2 = xp[ab + 4],   a3 = xp[ab + 164];
        u32 a4 = xp[ab + 8],   a5 = xp[ab + 168];
        u32 a6 = xp[ab + 12],  a7 = xp[ab + 172];

        int tn = tile + NBLK;
        if (tn < 625) {
            if (l2) { pA = g_agg[tn * 512 + tid]; pX = g_xr[tn * 512 + tid]; }
            else      pA = __ldg(&xin[tn * 512 + tid]);
        }

        int x4 = (gr & 3) * 4;
#pragma unroll
        for (int q = 0; q < 4; q++) {
            float c[4] = {0.f, 0.f, 0.f, 0.f};
            float d[4] = {0.f, 0.f, 0.f, 0.f};
            mma16816(c, a0, a1, a2, a3, Bf[q][0][0][0], Bf[q][0][0][1]);
            mma16816(c, a4, a5, a6, a7, Bf[q][0][1][0], Bf[q][0][1][1]);
            mma16816(d, a0, a1, a2, a3, Bf[q][1][0][0], Bf[q][1][0][1]);
            mma16816(d, a4, a5, a6, a7, Bf[q][1][1][0], Bf[q][1][1][1]);
            u64 p0 = ((u64)h2pack(d[0], d[1]) << 32) | h2pack(c[0], c[1]);
            u64 p1 = ((u64)h2pack(d[2], d[3]) << 32) | h2pack(c[2], c[3]);
            int c0 = w * 16 + q * 4 + tg;
            ts[gr * 256       + (c0 ^ x4)] = p0;
            ts[(gr + 8) * 256 + (c0 ^ x4)] = p1;
        }
        if (w < 8) {
            float c[4] = {0.f, 0.f, 0.f, 0.f};
            mma16816(c, a0, a1, a2, a3, Bs[0][0], Bs[0][1]);
            mma16816(c, a4, a5, a6, a7, Bs[1][0], Bs[1][1]);
            if (w < 4) {
                int o = w * 8 + 2 * tg;
                *(float2*)(g_xb + (nb + gr)     * 32 + o) = make_float2(c[0], c[1]);
                *(float2*)(g_xb + (nb + gr + 8) * 32 + o) = make_float2(c[2], c[3]);
            } else {
                int o = (w - 4) * 8 + 2 * tg;
                *(float2*)(g_xr + (nb + gr)     * 32 + o) =
                    make_float2(c[0] + biasv.x, c[1] + biasv.y);
                *(float2*)(g_xr + (nb + gr + 8) * 32 + o) =
                    make_float2(c[2] + biasv.x, c[3] + biasv.y);
            }
        }
        __syncthreads();

        u64* dst = g_T2 + (size_t)nb * 256;
#pragma unroll
        for (int r = 0; r < 8; r++) {
            int i64 = r * 512 + tid;
            int row = i64 >> 8, cc = i64 & 255;
            dst[i64] = ts[row * 256 + (cc ^ ((row & 3) * 4))];
        }
        __syncthreads();
    }
}

// ---- phase: edges. Per-warp loop over edge-quads (4 edges/iter, 8-lane quads) ----
__device__ void phase_edge(const float* __restrict__ ea, const int* __restrict__ ei,
                           const float* __restrict__ w1, const float* __restrict__ b1) {
    int lane = threadIdx.x & 31;
    int w = threadIdx.x >> 5;
    int grp = lane >> 3;
    int q = lane & 7;
    int base = lane & 24;

    // hoisted invariants
    float4 bvv = __ldg((const float4*)(b1 + 4 * q));
    float4 w0v = __ldg((const float4*)(w1 + 0 * 32 + 4 * q));
    float4 w1v = __ldg((const float4*)(w1 + 1 * 32 + 4 * q));
    float4 w2v = __ldg((const float4*)(w1 + 2 * 32 + 4 * q));
    float4 w3v = __ldg((const float4*)(w1 + 3 * 32 + 4 * q));
    __half2 z = __floats2half2_rn(0.f, 0.f);

    for (int task = blockIdx.x * 16 + w; task < Ee / 4; task += NBLK * 16) {
        int e = 4 * task + grp;
        int src = __ldg(&ei[e]);
        int dst = __ldg(&ei[Ee + e]);
        float4 a = __ldg((const float4*)ea + e);
        float h0 = fmaxf(bvv.x + a.x * w0v.x + a.y * w1v.x + a.z * w2v.x + a.w * w3v.x, 0.f);
        float h1 = fmaxf(bvv.y + a.x * w0v.y + a.y * w1v.y + a.z * w2v.y + a.w * w3v.y, 0.f);
        float h2v = fmaxf(bvv.z + a.x * w0v.z + a.y * w1v.z + a.z * w2v.z + a.w * w3v.z, 0.f);
        float h3 = fmaxf(bvv.w + a.x * w0v.w + a.y * w1v.w + a.z * w2v.w + a.w * w3v.w, 0.f);
        u32 hlo = h2pack(h0, h1);
        u32 hhi = h2pack(h2v, h3);

        float4 xbv = __ldg((const float4*)(g_xb + src * 32 + 4 * q));
        const uint4* Tp = (const uint4*)(g_T2 + (size_t)src * 256) + q;

        float r0 = xbv.x, r1 = xbv.y, r2 = xbv.z, r3 = xbv.w;
        __half2 aA01 = z, aB01 = z, aA23 = z, aB23 = z;
#pragma unroll
        for (int kp = 0; kp < 16; kp++) {
            u32 hh = __shfl_sync(0xffffffffu, (kp & 1) ? hhi : hlo, base + (kp >> 1));
            __half2 hph = *(__half2*)&hh;
            __half2 hA = __low2half2(hph);
            __half2 hB = __high2half2(hph);
            uint4 t = __ldg(&Tp[kp * 8]);
            aA01 = __hfma2(hA, *(__half2*)&t.x, aA01);
            aB01 = __hfma2(hB, *(__half2*)&t.y, aB01);
            aA23 = __hfma2(hA, *(__half2*)&t.z, aA23);
            aB23 = __hfma2(hB, *(__half2*)&t.w, aB23);
            if (kp == 7 || kp == 15) {
                float2 fA01 = __half22float2(aA01), fB01 = __half22float2(aB01);
                float2 fA23 = __half22float2(aA23), fB23 = __half22float2(aB23);
                r0 += fA01.x + fB01.x;  r1 += fA01.y + fB01.y;
                r2 += fA23.x + fB23.x;  r3 += fA23.y + fB23.y;
                aA01 = z; aB01 = z; aA23 = z; aB23 = z;
            }
        }
        red_add_v4(&g_agg[dst * 32 + 4 * q], r0, r1, r2, r3);
    }
}

// ---- fused persistent kernel ----
__global__ void __launch_bounds__(512, 1)
k_fused(const float* __restrict__ x, const float* __restrict__ ea,
        const float* __restrict__ e1w1, const float* __restrict__ e1b1,
        const float* __restrict__ e1w2, const float* __restrict__ e1b2,
        const float* __restrict__ root1, const float* __restrict__ bias1,
        const float* __restrict__ e2w1, const float* __restrict__ e2b1,
        const float* __restrict__ e2w2, const float* __restrict__ e2b2,
        const float* __restrict__ root2, const float* __restrict__ bias2,
        const float* __restrict__ bn1g, const float* __restrict__ bn1b,
        const float* __restrict__ bn1m, const float* __restrict__ bn1v,
        const float* __restrict__ bn2g, const float* __restrict__ bn2b,
        const float* __restrict__ bn2m, const float* __restrict__ bn2v,
        const float* __restrict__ r1w, const float* __restrict__ r1b,
        const float* __restrict__ r2w, const float* __restrict__ r2b,
        const int* __restrict__ eidx, const int* __restrict__ batch,
        float* __restrict__ out) {
    __shared__ __half xs[16 * 40];
    __shared__ u64 ts[16 * 256];

    // phase 1: deg histogram + T1/xb1/xr1 from x
    phase_T(x, e1w2, e1b2, root1, bias1, eidx,
            nullptr, nullptr, nullptr, nullptr, xs, ts);
    gbar();
    // phase 2: edges layer 1
    phase_edge(ea, eidx, e1w1, e1b1);
    gbar();
    // phase 3: T2/xb2/xr2 from h1 computed on the fly (BN1+ReLU); resets agg
    phase_T(nullptr, e2w2, e2b2, root2, bias2, nullptr,
            bn1g, bn1b, bn1m, bn1v, xs, ts);
    gbar();
    // phase 4: edges layer 2
    phase_edge(ea, eidx, e2w1, e2b1);
    gbar();
    // phase 5: node2 + mean-pool scatter; resets agg & deg
    for (int t = blockIdx.x * 512 + threadIdx.x; t < Nn * 8; t += NBLK * 512) {
        int n = t >> 3, q = t & 7;
        float4 ag = *(const float4*)(g_agg + n * 32 + 4 * q);
        float4 xr = *(const float4*)(g_xr + n * 32 + 4 * q);
        float inv = 1.f / fmaxf(g_deg[n], 1.f);
        *(float4*)(g_agg + n * 32 + 4 * q) = make_float4(0.f, 0.f, 0.f, 0.f);
        if (q == 0) g_deg[n] = 0.f;
        float4 g = __ldg((const float4*)(bn2g + 4 * q));
        float4 b = __ldg((const float4*)(bn2b + 4 * q));
        float4 m = __ldg((const float4*)(bn2m + 4 * q));
        float4 v = __ldg((const float4*)(bn2v + 4 * q));
        float rx = fmaxf((ag.x * inv + xr.x - m.x) * rsqrtf(v.x + BN_EPS) * g.x + b.x, 0.f);
        float ry = fmaxf((ag.y * inv + xr.y - m.y) * rsqrtf(v.y + BN_EPS) * g.y + b.y, 0.f);
        float rz = fmaxf((ag.z * inv + xr.z - m.z) * rsqrtf(v.z + BN_EPS) * g.z + b.z, 0.f);
        float rw = fmaxf((ag.w * inv + xr.w - m.w) * rsqrtf(v.w + BN_EPS) * g.w + b.w, 0.f);
        int gph = __ldg(&batch[n]);
        red_add_v4(&g_pool[gph * 32 + 4 * q], rx, ry, rz, rw);
        if (q == 0) atomicAdd(&g_pcnt[gph], 1.f);
    }
    gbar();
    // phase 6: readout (block 0, one thread per graph); resets pool/pcnt
    if (blockIdx.x == 0 && threadIdx.x < Gg) {
        int gph = threadIdx.x;
        float c = fmaxf(g_pcnt[gph], 1.f);
        float p[Cc];
#pragma unroll
        for (int o = 0; o < Cc; o++) p[o] = g_pool[gph * Cc + o] / c;
        float res = r2b[0];
#pragma unroll
        for (int jj = 0; jj < 16; jj++) {
            float hid = r1b[jj];
#pragma unroll
            for (int o = 0; o < Cc; o++) hid += p[o] * r1w[o * 16 + jj];
            res += fmaxf(hid, 0.f) * r2w[jj];
        }
        out[gph] = res;
#pragma unroll
        for (int o = 0; o < Cc; o++) g_pool[gph * Cc + o] = 0.f;
        g_pcnt[gph] = 0.f;
    }
}

extern "C" void kernel_launch(void* const* d_in, const int* in_sizes, int n_in,
                              void* d_out, int out_size) {
    const float* x     = (const float*)d_in[0];
    const float* ea    = (const float*)d_in[1];
    const float* e1w1  = (const float*)d_in[2];
    const float* e1b1  = (const float*)d_in[3];
    const float* e1w2  = (const float*)d_in[4];
    const float* e1b2  = (const float*)d_in[5];
    const float* root1 = (const float*)d_in[6];
    const float* bias1 = (const float*)d_in[7];
    const float* e2w1  = (const float*)d_in[8];
    const float* e2b1  = (const float*)d_in[9];
    const float* e2w2  = (const float*)d_in[10];
    const float* e2b2  = (const float*)d_in[11];
    const float* root2 = (const float*)d_in[12];
    const float* bias2 = (const float*)d_in[13];
    const float* bn1g  = (const float*)d_in[14];
    const float* bn1b  = (const float*)d_in[15];
    const float* bn1m  = (const float*)d_in[16];
    const float* bn1v  = (const float*)d_in[17];
    const float* bn2g  = (const float*)d_in[18];
    const float* bn2b  = (const float*)d_in[19];
    const float* bn2m  = (const float*)d_in[20];
    const float* bn2v  = (const float*)d_in[21];
    const float* r1w   = (const float*)d_in[22];
    const float* r1b   = (const float*)d_in[23];
    const float* r2w   = (const float*)d_in[24];
    const float* r2b   = (const float*)d_in[25];
    const int*   eidx  = (const int*)d_in[26];
    const int*   batch = (const int*)d_in[27];
    float* out = (float*)d_out;

    k_fused<<<NBLK, 512>>>(x, ea,
                           e1w1, e1b1, e1w2, e1b2, root1, bias1,
                           e2w1, e2b1, e2w2, e2b2, root2, bias2,
                           bn1g, bn1b, bn1m, bn1v,
                           bn2g, bn2b, bn2m, bn2v,
                           r1w, r1b, r2w, r2b,
                           eidx, batch, out);
}

// round 16
// speedup vs baseline: 1.0227x; 1.0227x over previous
#include <cuda_runtime.h>
#include <cuda_fp16.h>

#define Nn 10000
#define Ee 100000
#define Cc 32
#define Gg 64
#define BN_EPS 1e-5f
#define NBLK 148

typedef unsigned long long u64;
typedef unsigned int u32;

// ---- scratch (static device globals; zero-initialized at load) ----
__device__ __align__(16) u64   g_T2[(size_t)Nn * 256];   // 20.48 MB fp16 T
__device__ __align__(16) float g_xb[Nn * Cc];
__device__ __align__(16) float g_xr[Nn * Cc];
__device__ __align__(16) float g_agg[Nn * Cc];
__device__ float g_deg[Nn];
__device__ __align__(16) float g_pool[Gg * Cc];
__device__ float g_pcnt[Gg];
__device__ unsigned g_cnt;                 // barrier count (self-resetting)
__device__ unsigned g_sense;               // barrier sense (monotonic; replay-safe)

__device__ __forceinline__ void red_add_v4(float* addr, float a, float b, float c, float d) {
    asm volatile("red.global.add.v4.f32 [%0], {%1, %2, %3, %4};"
                 :: "l"(addr), "f"(a), "f"(b), "f"(c), "f"(d) : "memory");
}
__device__ __forceinline__ u32 h2pack(float lo, float hi) {
    __half2 h = __floats2half2_rn(lo, hi);
    return *(u32*)&h;
}
__device__ __forceinline__ void mma16816(float c[4], u32 a0, u32 a1, u32 a2, u32 a3,
                                         u32 b0, u32 b1) {
    asm("mma.sync.aligned.m16n8k16.row.col.f32.f16.f16.f32 "
        "{%0,%1,%2,%3}, {%4,%5,%6,%7}, {%8,%9}, {%0,%1,%2,%3};"
        : "+f"(c[0]), "+f"(c[1]), "+f"(c[2]), "+f"(c[3])
        : "r"(a0), "r"(a1), "r"(a2), "r"(a3), "r"(b0), "r"(b1));
}

// ---- grid barrier: sense-reversing, count self-reset by last arriver ----
__device__ __forceinline__ void gbar() {
    __syncthreads();
    if (threadIdx.x == 0) {
        __threadfence();
        unsigned s = *(volatile unsigned*)&g_sense;
        unsigned old = atomicAdd(&g_cnt, 1u);
        if (old == NBLK - 1) {
            g_cnt = 0;
            __threadfence();
            atomicAdd(&g_sense, 1u);
        } else {
            while (*(volatile unsigned*)&g_sense == s) {}
        }
        __threadfence();
    }
    __syncthreads();
}

// ---- phase: T = x@w2 (HMMA) + xb = x@b2 (warps 0-3) + xr = x@root + bias (warps 4-7) ----
__device__ void phase_T(const float* __restrict__ xin, const float* __restrict__ w2,
                        const float* __restrict__ b2, const float* __restrict__ root,
                        const float* __restrict__ bias, const int* __restrict__ ei,
                        const float* __restrict__ bg, const float* __restrict__ bb,
                        const float* __restrict__ bm, const float* __restrict__ bv,
                        __half* xs, u64* ts) {
    int tid = threadIdx.x;
    int lane = tid & 31;
    int w = tid >> 5;
    int tg = lane & 3;
    int gr = lane >> 2;
    bool l2 = (bg != nullptr);

    if (ei) {
        for (int e = blockIdx.x * 512 + tid; e < Ee; e += NBLK * 512)
            atomicAdd(&g_deg[__ldg(&ei[Ee + e])], 1.f);
    }

    u32 Bf[4][2][2][2];
#pragma unroll
    for (int q = 0; q < 4; q++)
#pragma unroll
        for (int kk = 0; kk < 2; kk++) {
            const float* rb = w2 + (2 * w + kk) * 1024 + q * 8 + gr;
#pragma unroll
            for (int st = 0; st < 2; st++) {
                int i0 = 2 * tg + 16 * st;
                Bf[q][kk][st][0] = h2pack(__ldg(&rb[i0 * 32]),       __ldg(&rb[(i0 + 1) * 32]));
                Bf[q][kk][st][1] = h2pack(__ldg(&rb[(i0 + 8) * 32]), __ldg(&rb[(i0 + 9) * 32]));
            }
        }
    u32 Bs[2][2] = {};
    float2 biasv = make_float2(0.f, 0.f);
    if (w < 8) {
        const float* src = (w < 4) ? (b2 + w * 8 + gr) : (root + (w - 4) * 8 + gr);
#pragma unroll
        for (int st = 0; st < 2; st++) {
            int i0 = 2 * tg + 16 * st;
            Bs[st][0] = h2pack(__ldg(&src[i0 * 32]),       __ldg(&src[(i0 + 1) * 32]));
            Bs[st][1] = h2pack(__ldg(&src[(i0 + 8) * 32]), __ldg(&src[(i0 + 9) * 32]));
        }
        if (w >= 4) biasv = __ldg((const float2*)(bias + (w - 4) * 8 + 2 * tg));
    }

    float scale = 0.f, shift = 0.f;
    if (l2) {
        int i = tid & 31;
        float s = rsqrtf(__ldg(&bv[i]) + BN_EPS) * __ldg(&bg[i]);
        scale = s;
        shift = __ldg(&bb[i]) - __ldg(&bm[i]) * s;
    }

    int tile = blockIdx.x;
    float pA = 0.f, pX = 0.f;
    if (tile < 625) {
        if (l2) { pA = g_agg[tile * 512 + tid]; pX = g_xr[tile * 512 + tid]; }
        else      pA = __ldg(&xin[tile * 512 + tid]);
    }

    for (; tile < 625; tile += NBLK) {
        int nb = tile * 16;
        int j = tid >> 5, i = tid & 31;
        float xv;
        if (l2) {
            float dg = fmaxf(g_deg[nb + j], 1.f);
            xv = fmaxf((pA / dg + pX) * scale + shift, 0.f);
            g_agg[tile * 512 + tid] = 0.f;
        } else xv = pA;
        xs[j * 40 + i] = __float2half(xv);
        __syncthreads();

        const u32* xp = (const u32*)xs;
        int ab = gr * 20 + tg;
        u32 a0 = xp[ab],       a1 = xp[ab + 160];
        u32 a2 = xp[ab + 4],   a3 = xp[ab + 164];
        u32 a4 = xp[ab + 8],   a5 = xp[ab + 168];
        u32 a6 = xp[ab + 12],  a7 = xp[ab + 172];

        int tn = tile + NBLK;
        if (tn < 625) {
            if (l2) { pA = g_agg[tn * 512 + tid]; pX = g_xr[tn * 512 + tid]; }
            else      pA = __ldg(&xin[tn * 512 + tid]);
        }

        int x4 = (gr & 3) * 4;
#pragma unroll
        for (int q = 0; q < 4; q++) {
            float c[4] = {0.f, 0.f, 0.f, 0.f};
            float d[4] = {0.f, 0.f, 0.f, 0.f};
            mma16816(c, a0, a1, a2, a3, Bf[q][0][0][0], Bf[q][0][0][1]);
            mma16816(c, a4, a5, a6, a7, Bf[q][0][1][0], Bf[q][0][1][1]);
            mma16816(d, a0, a1, a2, a3, Bf[q][1][0][0], Bf[q][1][0][1]);
            mma16816(d, a4, a5, a6, a7, Bf[q][1][1][0], Bf[q][1][1][1]);
            u64 p0 = ((u64)h2pack(d[0], d[1]) << 32) | h2pack(c[0], c[1]);
            u64 p1 = ((u64)h2pack(d[2], d[3]) << 32) | h2pack(c[2], c[3]);
            int c0 = w * 16 + q * 4 + tg;
            ts[gr * 256       + (c0 ^ x4)] = p0;
            ts[(gr + 8) * 256 + (c0 ^ x4)] = p1;
        }
        if (w < 8) {
            float c[4] = {0.f, 0.f, 0.f, 0.f};
            mma16816(c, a0, a1, a2, a3, Bs[0][0], Bs[0][1]);
            mma16816(c, a4, a5, a6, a7, Bs[1][0], Bs[1][1]);
            if (w < 4) {
                int o = w * 8 + 2 * tg;
                *(float2*)(g_xb + (nb + gr)     * 32 + o) = make_float2(c[0], c[1]);
                *(float2*)(g_xb + (nb + gr + 8) * 32 + o) = make_float2(c[2], c[3]);
            } else {
                int o = (w - 4) * 8 + 2 * tg;
                *(float2*)(g_xr + (nb + gr)     * 32 + o) =
                    make_float2(c[0] + biasv.x, c[1] + biasv.y);
                *(float2*)(g_xr + (nb + gr + 8) * 32 + o) =
                    make_float2(c[2] + biasv.x, c[3] + biasv.y);
            }
        }
        __syncthreads();

        u64* dst = g_T2 + (size_t)nb * 256;
#pragma unroll
        for (int r = 0; r < 8; r++) {
            int i64 = r * 512 + tid;
            int row = i64 >> 8, cc = i64 & 255;
            dst[i64] = ts[row * 256 + (cc ^ ((row & 3) * 4))];
        }
        __syncthreads();
    }
}

// ---- phase: edges. TWO independent 4-edge tasks per warp-iteration (8 edges, MLP x2) ----
__device__ void phase_edge(const float* __restrict__ ea, const int* __restrict__ ei,
                           const float* __restrict__ w1, const float* __restrict__ b1) {
    int lane = threadIdx.x & 31;
    int w = threadIdx.x >> 5;
    int grp = lane >> 3;
    int q = lane & 7;
    int base = lane & 24;

    float4 bvv = __ldg((const float4*)(b1 + 4 * q));
    float4 w0v = __ldg((const float4*)(w1 + 0 * 32 + 4 * q));
    float4 w1v = __ldg((const float4*)(w1 + 1 * 32 + 4 * q));
    float4 w2v = __ldg((const float4*)(w1 + 2 * 32 + 4 * q));
    float4 w3v = __ldg((const float4*)(w1 + 3 * 32 + 4 * q));
    __half2 z = __floats2half2_rn(0.f, 0.f);

    // 12500 pair-tasks of 8 edges
    for (int task = blockIdx.x * 16 + w; task < Ee / 8; task += NBLK * 16) {
        int eA = 8 * task + grp;
        int eB = 8 * task + 4 + grp;
        int srcA = __ldg(&ei[eA]),      srcB = __ldg(&ei[eB]);
        int dstA = __ldg(&ei[Ee + eA]), dstB = __ldg(&ei[Ee + eB]);
        float4 aA = __ldg((const float4*)ea + eA);
        float4 aB = __ldg((const float4*)ea + eB);

        float hA0 = fmaxf(bvv.x + aA.x * w0v.x + aA.y * w1v.x + aA.z * w2v.x + aA.w * w3v.x, 0.f);
        float hA1 = fmaxf(bvv.y + aA.x * w0v.y + aA.y * w1v.y + aA.z * w2v.y + aA.w * w3v.y, 0.f);
        float hA2 = fmaxf(bvv.z + aA.x * w0v.z + aA.y * w1v.z + aA.z * w2v.z + aA.w * w3v.z, 0.f);
        float hA3 = fmaxf(bvv.w + aA.x * w0v.w + aA.y * w1v.w + aA.z * w2v.w + aA.w * w3v.w, 0.f);
        float hB0 = fmaxf(bvv.x + aB.x * w0v.x + aB.y * w1v.x + aB.z * w2v.x + aB.w * w3v.x, 0.f);
        float hB1 = fmaxf(bvv.y + aB.x * w0v.y + aB.y * w1v.y + aB.z * w2v.y + aB.w * w3v.y, 0.f);
        float hB2 = fmaxf(bvv.z + aB.x * w0v.z + aB.y * w1v.z + aB.z * w2v.z + aB.w * w3v.z, 0.f);
        float hB3 = fmaxf(bvv.w + aB.x * w0v.w + aB.y * w1v.w + aB.z * w2v.w + aB.w * w3v.w, 0.f);
        u32 hAlo = h2pack(hA0, hA1), hAhi = h2pack(hA2, hA3);
        u32 hBlo = h2pack(hB0, hB1), hBhi = h2pack(hB2, hB3);

        float4 xbA = __ldg((const float4*)(g_xb + srcA * 32 + 4 * q));
        float4 xbB = __ldg((const float4*)(g_xb + srcB * 32 + 4 * q));
        const uint4* TpA = (const uint4*)(g_T2 + (size_t)srcA * 256) + q;
        const uint4* TpB = (const uint4*)(g_T2 + (size_t)srcB * 256) + q;

        float rA0 = xbA.x, rA1 = xbA.y, rA2 = xbA.z, rA3 = xbA.w;
        float rB0 = xbB.x, rB1 = xbB.y, rB2 = xbB.z, rB3 = xbB.w;
        __half2 aAA01 = z, aAB01 = z, aAA23 = z, aAB23 = z;
        __half2 aBA01 = z, aBB01 = z, aBA23 = z, aBB23 = z;
#pragma unroll
        for (int kp = 0; kp < 16; kp++) {
            uint4 tA = __ldg(&TpA[kp * 8]);
            uint4 tB = __ldg(&TpB[kp * 8]);
            u32 hhA = __shfl_sync(0xffffffffu, (kp & 1) ? hAhi : hAlo, base + (kp >> 1));
            u32 hhB = __shfl_sync(0xffffffffu, (kp & 1) ? hBhi : hBlo, base + (kp >> 1));
            __half2 hphA = *(__half2*)&hhA;
            __half2 hphB = *(__half2*)&hhB;
            __half2 hAa = __low2half2(hphA), hAb = __high2half2(hphA);
            __half2 hBa = __low2half2(hphB), hBb = __high2half2(hphB);
            aAA01 = __hfma2(hAa, *(__half2*)&tA.x, aAA01);
            aAB01 = __hfma2(hAb, *(__half2*)&tA.y, aAB01);
            aAA23 = __hfma2(hAa, *(__half2*)&tA.z, aAA23);
            aAB23 = __hfma2(hAb, *(__half2*)&tA.w, aAB23);
            aBA01 = __hfma2(hBa, *(__half2*)&tB.x, aBA01);
            aBB01 = __hfma2(hBb, *(__half2*)&tB.y, aBB01);
            aBA23 = __hfma2(hBa, *(__half2*)&tB.z, aBA23);
            aBB23 = __hfma2(hBb, *(__half2*)&tB.w, aBB23);
            if (kp == 7 || kp == 15) {          // flush to fp32 (chains <= 8 adds)
                float2 f;
                f = __half22float2(aAA01); rA0 += f.x; rA1 += f.y;
                f = __half22float2(aAB01); rA0 += f.x; rA1 += f.y;
                f = __half22float2(aAA23); rA2 += f.x; rA3 += f.y;
                f = __half22float2(aAB23); rA2 += f.x; rA3 += f.y;
                f = __half22float2(aBA01); rB0 += f.x; rB1 += f.y;
                f = __half22float2(aBB01); rB0 += f.x; rB1 += f.y;
                f = __half22float2(aBA23); rB2 += f.x; rB3 += f.y;
                f = __half22float2(aBB23); rB2 += f.x; rB3 += f.y;
                aAA01 = z; aAB01 = z; aAA23 = z; aAB23 = z;
                aBA01 = z; aBB01 = z; aBA23 = z; aBB23 = z;
            }
        }
        red_add_v4(&g_agg[dstA * 32 + 4 * q], rA0, rA1, rA2, rA3);
        red_add_v4(&g_agg[dstB * 32 + 4 * q], rB0, rB1, rB2, rB3);
    }
}

// ---- fused persistent kernel ----
__global__ void __launch_bounds__(512, 1)
k_fused(const float* __restrict__ x, const float* __restrict__ ea,
        const float* __restrict__ e1w1, const float* __restrict__ e1b1,
        const float* __restrict__ e1w2, const float* __restrict__ e1b2,
        const float* __restrict__ root1, const float* __restrict__ bias1,
        const float* __restrict__ e2w1, const float* __restrict__ e2b1,
        const float* __restrict__ e2w2, const float* __restrict__ e2b2,
        const float* __restrict__ root2, const float* __restrict__ bias2,
        const float* __restrict__ bn1g, const float* __restrict__ bn1b,
        const float* __restrict__ bn1m, const float* __restrict__ bn1v,
        const float* __restrict__ bn2g, const float* __restrict__ bn2b,
        const float* __restrict__ bn2m, const float* __restrict__ bn2v,
        const float* __restrict__ r1w, const float* __restrict__ r1b,
        const float* __restrict__ r2w, const float* __restrict__ r2b,
        const int* __restrict__ eidx, const int* __restrict__ batch,
        float* __restrict__ out) {
    __shared__ __half xs[16 * 40];
    __shared__ u64 ts[16 * 256];

    // phase 1: deg histogram + T1/xb1/xr1 from x
    phase_T(x, e1w2, e1b2, root1, bias1, eidx,
            nullptr, nullptr, nullptr, nullptr, xs, ts);
    gbar();
    // phase 2: edges layer 1
    phase_edge(ea, eidx, e1w1, e1b1);
    gbar();
    // phase 3: T2/xb2/xr2 from h1 computed on the fly (BN1+ReLU); resets agg
    phase_T(nullptr, e2w2, e2b2, root2, bias2, nullptr,
            bn1g, bn1b, bn1m, bn1v, xs, ts);
    gbar();
    // phase 4: edges layer 2
    phase_edge(ea, eidx, e2w1, e2b1);
    gbar();
    // phase 5: node2 + mean-pool scatter; resets agg & deg
    for (int t = blockIdx.x * 512 + threadIdx.x; t < Nn * 8; t += NBLK * 512) {
        int n = t >> 3, q = t & 7;
        float4 ag = *(const float4*)(g_agg + n * 32 + 4 * q);
        float4 xr = *(const float4*)(g_xr + n * 32 + 4 * q);
        float inv = 1.f / fmaxf(g_deg[n], 1.f);
        *(float4*)(g_agg + n * 32 + 4 * q) = make_float4(0.f, 0.f, 0.f, 0.f);
        if (q == 0) g_deg[n] = 0.f;
        float4 g = __ldg((const float4*)(bn2g + 4 * q));
        float4 b = __ldg((const float4*)(bn2b + 4 * q));
        float4 m = __ldg((const float4*)(bn2m + 4 * q));
        float4 v = __ldg((const float4*)(bn2v + 4 * q));
        float rx = fmaxf((ag.x * inv + xr.x - m.x) * rsqrtf(v.x + BN_EPS) * g.x + b.x, 0.f);
        float ry = fmaxf((ag.y * inv + xr.y - m.y) * rsqrtf(v.y + BN_EPS) * g.y + b.y, 0.f);
        float rz = fmaxf((ag.z * inv + xr.z - m.z) * rsqrtf(v.z + BN_EPS) * g.z + b.z, 0.f);
        float rw = fmaxf((ag.w * inv + xr.w - m.w) * rsqrtf(v.w + BN_EPS) * g.w + b.w, 0.f);
        int gph = __ldg(&batch[n]);
        red_add_v4(&g_pool[gph * 32 + 4 * q], rx, ry, rz, rw);
        if (q == 0) atomicAdd(&g_pcnt[gph], 1.f);
    }
    gbar();
    // phase 6: readout (block 0, one thread per graph); resets pool/pcnt
    if (blockIdx.x == 0 && threadIdx.x < Gg) {
        int gph = threadIdx.x;
        float c = fmaxf(g_pcnt[gph], 1.f);
        float p[Cc];
#pragma unroll
        for (int o = 0; o < Cc; o++) p[o] = g_pool[gph * Cc + o] / c;
        float res = r2b[0];
#pragma unroll
        for (int jj = 0; jj < 16; jj++) {
            float hid = r1b[jj];
#pragma unroll
            for (int o = 0; o < Cc; o++) hid += p[o] * r1w[o * 16 + jj];
            res += fmaxf(hid, 0.f) * r2w[jj];
        }
        out[gph] = res;
#pragma unroll
        for (int o = 0; o < Cc; o++) g_pool[gph * Cc + o] = 0.f;
        g_pcnt[gph] = 0.f;
    }
}

extern "C" void kernel_launch(void* const* d_in, const int* in_sizes, int n_in,
                              void* d_out, int out_size) {
    const float* x     = (const float*)d_in[0];
    const float* ea    = (const float*)d_in[1];
    const float* e1w1  = (const float*)d_in[2];
    const float* e1b1  = (const float*)d_in[3];
    const float* e1w2  = (const float*)d_in[4];
    const float* e1b2  = (const float*)d_in[5];
    const float* root1 = (const float*)d_in[6];
    const float* bias1 = (const float*)d_in[7];
    const float* e2w1  = (const float*)d_in[8];
    const float* e2b1  = (const float*)d_in[9];
    const float* e2w2  = (const float*)d_in[10];
    const float* e2b2  = (const float*)d_in[11];
    const float* root2 = (const float*)d_in[12];
    const float* bias2 = (const float*)d_in[13];
    const float* bn1g  = (const float*)d_in[14];
    const float* bn1b  = (const float*)d_in[15];
    const float* bn1m  = (const float*)d_in[16];
    const float* bn1v  = (const float*)d_in[17];
    const float* bn2g  = (const float*)d_in[18];
    const float* bn2b  = (const float*)d_in[19];
    const float* bn2m  = (const float*)d_in[20];
    const float* bn2v  = (const float*)d_in[21];
    const float* r1w   = (const float*)d_in[22];
    const float* r1b   = (const float*)d_in[23];
    const float* r2w   = (const float*)d_in[24];
    const float* r2b   = (const float*)d_in[25];
    const int*   eidx  = (const int*)d_in[26];
    const int*   batch = (const int*)d_in[27];
    float* out = (float*)d_out;

    k_fused<<<NBLK, 512>>>(x, ea,
                           e1w1, e1b1, e1w2, e1b2, root1, bias1,
                           e2w1, e2b1, e2w2, e2b2, root2, bias2,
                           bn1g, bn1b, bn1m, bn1v,
                           bn2g, bn2b, bn2m, bn2v,
                           r1w, r1b, r2w, r2b,
                           eidx, batch, out);
}